// round 7
// baseline (speedup 1.0000x reference)
#include <cuda_runtime.h>
#include <stdint.h>

#define GS 128            // grid dim
#define VX 132            // vol8 x-stride (padded from 129; 33 words)
#define VY 129
#define VZ 129
#define VTOT (VZ*VY*VX)   // 2,196,612 bytes
#define BT  288           // fused-build block threads (9 warps)

// Packed neighborhood volume: byte at (z,y,x) (z,y,x in [0,129))
// holds bits of grid[z-1+dz][y-1+dy][x-1+dx] (0 if OOB) at bit dz*4+dy*2+dx.
__device__ uint8_t g_vol8[VTOT];

// ---- Fused kernel: grid floats -> vol8 tile, via per-block smem bitmask ----
// Block b = z*5 + yq: writes vol8 plane z, y in [32*yq, 32*yq+ny), ny=min(32,129-32yq).
// Needs grid planes gz = z-1, z and grid rows gy0..gy0+nr-1 (gy0 = 32yq-1, nr = ny+1).
__global__ void __launch_bounds__(BT)
fused_build_kernel(const float4* __restrict__ grid4) {
    int z  = blockIdx.x / 5;          // 0..128
    int yq = blockIdx.x % 5;          // 0..4
    int y0 = yq * 32;
    int ny = min(32, VY - y0);        // 32 or 1
    int nr = ny + 1;                  // grid rows needed
    int gy0 = y0 - 1;

    // bits[p][r][w]: bit i of word w = grid[z-1+p][gy0+r][32w+i] (0 if OOB)
    __shared__ uint32_t bits[2][33][4];

    // ---- pack phase: each group of 8 lanes builds one 32-bit word ----
    // float4 task idx -> (p, r, q): p plane, r row, q float4-within-row (0..31)
    int ntask4 = 2 * nr * 32;         // multiple of 8 and of 32
    int tid = threadIdx.x;
    for (int base = 0; base < ntask4; base += BT) {
        int idx = base + tid;          // idx%32 == lane (BT, base multiples of 32)
        bool active = idx < ntask4;
        unsigned nib = 0;
        int p = 0, r = 0, q = 0;
        if (active) {
            p = idx / (nr * 32);
            int rem = idx % (nr * 32);
            r = rem / 32;
            q = rem % 32;
            int gz = z - 1 + p;
            int gy = gy0 + r;
            if (gz >= 0 && gz < GS && gy >= 0 && gy < GS) {
                float4 v = __ldg(&grid4[gz * 4096 + gy * 32 + q]);
                nib = (v.x != 0.0f ? 1u : 0u)
                    | (v.y != 0.0f ? 2u : 0u)
                    | (v.z != 0.0f ? 4u : 0u)
                    | (v.w != 0.0f ? 8u : 0u);
            }
        }
        unsigned word = nib << (4 * (tid & 7));
        word |= __shfl_xor_sync(0xffffffffu, word, 1);
        word |= __shfl_xor_sync(0xffffffffu, word, 2);
        word |= __shfl_xor_sync(0xffffffffu, word, 4);
        if (active && (idx & 7) == 0)
            bits[p][r][q / 8] = word;
    }
    __syncthreads();

    // ---- emit phase: task = (local row rl, chunk c) ----
    // Chunk c covers x_out = 32c..32c+31; chunk 4 writes only 1 word
    // (x=128..131, 129-131 pad) to avoid spilling into the next row.
    int ntask = ny * 5;               // <= 160 <= BT
    if (tid < ntask) {
        int c  = tid % 5;
        int rl = tid / 5;             // vol8 y = y0 + rl
        // v[e] (e = dz*2+dy): 64-bit window of bits covering x = 32(c-1)..32c+31
        uint64_t v[4];
#pragma unroll
        for (int dz = 0; dz < 2; ++dz) {
#pragma unroll
            for (int dy = 0; dy < 2; ++dy) {
                // grid row gy0 + (rl + dy) -> smem row rl+dy (< nr)
                uint32_t lo = (c > 0) ? bits[dz][rl + dy][c - 1] : 0u;
                uint32_t hi = (c < 4) ? bits[dz][rl + dy][c]     : 0u;
                v[dz * 2 + dy] = ((uint64_t)hi << 32) | (uint64_t)lo;
            }
        }
        int nw = (c == 4) ? 1 : 8;
        uint32_t* dst = (uint32_t*)&g_vol8[(size_t)(z * VY + (y0 + rl)) * VX + 32 * c];
#pragma unroll
        for (int w = 0; w < 8; ++w) {
            if (w >= nw) break;
            uint32_t acc = 0;
#pragma unroll
            for (int j = 0; j < 4; ++j) {
                int k = w * 4 + j;
                unsigned byte = 0;
#pragma unroll
                for (int e = 0; e < 4; ++e)
                    byte |= (unsigned)((v[e] >> (31 + k)) & 3ull) << (2 * e);
                acc |= byte << (8 * j);
            }
            dst[w] = acc;
        }
    }
}

// ---- Sample kernel (unchanged from R6: interleaved, 4 pts/thread) ----
__device__ __forceinline__ float sample_one(float x, float y, float z) {
    float ix = ((x + 1.0f) * 128.0f - 1.0f) * 0.5f;
    float iy = ((y + 1.0f) * 128.0f - 1.0f) * 0.5f;
    float iz = ((z + 1.0f) * 128.0f - 1.0f) * 0.5f;
    float fx = floorf(ix), fy = floorf(iy), fz = floorf(iz);
    float wx = ix - fx, wy = iy - fy, wz = iz - fz;
    int ix0 = (int)fx, iy0 = (int)fy, iz0 = (int)fz;
    // coords in [-1,1] -> base in [-1,127]; clamp only for memory safety
    ix0 = min(127, max(-1, ix0));
    iy0 = min(127, max(-1, iy0));
    iz0 = min(127, max(-1, iz0));
    int idx = ((iz0 + 1) * VY + (iy0 + 1)) * VX + (ix0 + 1);
    unsigned b = (unsigned)__ldg(&g_vol8[idx]);

    float f0 = (float)( b       & 1u);
    float f1 = (float)((b >> 1) & 1u);
    float f2 = (float)((b >> 2) & 1u);
    float f3 = (float)((b >> 3) & 1u);
    float f4 = (float)((b >> 4) & 1u);
    float f5 = (float)((b >> 5) & 1u);
    float f6 = (float)((b >> 6) & 1u);
    float f7 = (float)((b >> 7) & 1u);

    float c00 = fmaf(wx, f1 - f0, f0);
    float c10 = fmaf(wx, f3 - f2, f2);
    float c01 = fmaf(wx, f5 - f4, f4);
    float c11 = fmaf(wx, f7 - f6, f6);
    float c0  = fmaf(wy, c10 - c00, c00);
    float c1  = fmaf(wy, c11 - c01, c01);
    return fmaf(wz, c1 - c0, c0);
}

// coords/out use streaming hints (evict-first) so the 2.2MB vol8 table keeps
// L1 residency for the gathers.
__global__ void sample_kernel(const float4* __restrict__ coords4,
                              float4* __restrict__ out4, int n4) {
    int tid = blockIdx.x * blockDim.x + threadIdx.x;
    if (tid >= n4) return;
    float4 a = __ldcs(&coords4[(size_t)tid * 3 + 0]);
    float4 b = __ldcs(&coords4[(size_t)tid * 3 + 1]);
    float4 c = __ldcs(&coords4[(size_t)tid * 3 + 2]);

    float4 o;
    o.x = sample_one(a.x, a.y, a.z);
    o.y = sample_one(a.w, b.x, b.y);
    o.z = sample_one(b.z, b.w, c.x);
    o.w = sample_one(c.y, c.z, c.w);
    __stcs(&out4[tid], o);
}

extern "C" void kernel_launch(void* const* d_in, const int* in_sizes, int n_in,
                              void* d_out, int out_size) {
    const float* grid   = (const float*)d_in[0];   // 128^3 floats
    const float* coords = (const float*)d_in[1];   // N*3 floats
    float* out = (float*)d_out;                    // N floats

    // 1) fused: grid -> packed neighborhood volume (one kernel)
    fused_build_kernel<<<VZ * 5, BT>>>((const float4*)grid);

    // 2) sample
    {
        int n  = in_sizes[1] / 3;                  // 8,388,608
        int n4 = n / 4;                            // 2,097,152
        sample_kernel<<<n4 / 256, 256>>>((const float4*)coords,
                                         (float4*)out, n4);
    }
}